// round 4
// baseline (speedup 1.0000x reference)
#include <cuda_runtime.h>
#include <cooperative_groups.h>
#include <cstdint>

namespace cg = cooperative_groups;

#define T_STEPS 2048
#define V_SZ    2048
#define G_SZ    24
#define K_SZ    512
#define CLUSTER_N 8
#define JPB     64              // columns of Wh per CTA
#define NCLUSTERS 16            // 16 clusters * 3 recurrences = 48
#define NBLOCKS (NCLUSTERS * CLUSTER_N)
#define THREADS_RNN 256

// ---------------- mbarrier helpers ----------------
#define MBARRIER_INIT(addr, count) \
    asm volatile("mbarrier.init.shared.b64 [%0], %1;" :: "r"((uint32_t)(addr)), "r"((uint32_t)(count)) : "memory")

// cluster-scope acquire wait (consumer of remote DSMEM stores)
#define MBARRIER_WAIT_PARITY_CL(mbar_smem_addr, phase_parity) do { \
    uint32_t _mbar = (uint32_t)(mbar_smem_addr); \
    uint32_t _parity = (uint32_t)(phase_parity); \
    uint32_t _done; \
    asm volatile( \
        "{\n\t" \
        ".reg .pred p;\n\t" \
        "mbarrier.try_wait.parity.acquire.cluster.shared::cta.b64 p, [%1], %2;\n\t" \
        "selp.b32 %0, 1, 0, p;\n\t" \
        "}" \
        : "=r"(_done) : "r"(_mbar), "r"(_parity) : "memory"); \
    if (!_done) { \
        asm volatile( \
            "{\n\t" \
            ".reg .pred P1;\n\t" \
            "WAIT_LOOP_%=:\n\t" \
            "mbarrier.try_wait.parity.acquire.cluster.shared::cta.b64 P1, [%0], %1, 0x989680;\n\t" \
            "@P1 bra.uni WAIT_DONE_%=;\n\t" \
            "bra.uni WAIT_LOOP_%=;\n\t" \
            "WAIT_DONE_%=:\n\t" \
            "}" \
            :: "r"(_mbar), "r"(_parity) : "memory"); \
    } \
} while(0)

__device__ __forceinline__ uint32_t s2u(const void* p) {
    uint32_t a;
    asm("{ .reg .u64 t; cvta.to.shared.u64 t, %1; cvt.u32.u64 %0, t; }" : "=r"(a) : "l"(p));
    return a;
}

__device__ __forceinline__ void ffma2(unsigned long long& acc,
                                      unsigned long long h2,
                                      unsigned long long w2) {
    asm("fma.rn.f32x2 %0, %1, %2, %0;" : "+l"(acc) : "l"(h2), "l"(w2));
}

__device__ __forceinline__ unsigned long long packf2(float lo, float hi) {
    unsigned long long r;
    asm("mov.b64 %0, {%1, %2};" : "=l"(r) : "f"(lo), "f"(hi));
    return r;
}

__device__ __forceinline__ float sum2(unsigned long long acc) {
    float lo, hi;
    asm("mov.b64 {%0, %1}, %2;" : "=f"(lo), "=f"(hi) : "l"(acc));
    return lo + hi;
}

// Scratch (no cudaMalloc allowed)
__device__ float g_P[V_SZ * K_SZ];       // P = W_e @ Wx + b   (V, K)
__device__ int   g_idx[T_STEPS * G_SZ];  // idx[t,g] = perms[g, token_t]

// ---------------------------------------------------------------------------
// Kernel 1: recover tokens from one-hot rows, build gather index table
// ---------------------------------------------------------------------------
__global__ void token_kernel(const float* __restrict__ seq,
                             const int* __restrict__ perms) {
    int t = blockIdx.x;
    __shared__ int tok;
    const float* row = seq + (size_t)t * V_SZ;
    for (int v = threadIdx.x; v < V_SZ; v += blockDim.x)
        if (row[v] > 0.5f) tok = v;
    __syncthreads();
    if (threadIdx.x < G_SZ)
        g_idx[t * G_SZ + threadIdx.x] = perms[threadIdx.x * V_SZ + tok];
}

// ---------------------------------------------------------------------------
// Kernel 2: P = W_e @ Wx + b  (2048x512 @ 512x512)
// ---------------------------------------------------------------------------
__global__ void __launch_bounds__(256)
gemm_P_kernel(const float* __restrict__ We,
              const float* __restrict__ Wx,
              const float* __restrict__ b) {
    __shared__ float sA[64][17];
    __shared__ float sB[16][68];
    int tid = threadIdx.x;
    int tx = tid & 15, ty = tid >> 4;
    int row0 = blockIdx.y * 64;
    int col0 = blockIdx.x * 64;
    float acc[4][4] = {};

    for (int kc = 0; kc < K_SZ; kc += 16) {
        {
            int v  = tid >> 2;
            int c4 = (tid & 3) * 4;
            float4 av = *(const float4*)&We[(size_t)(row0 + v) * K_SZ + kc + c4];
            sA[v][c4 + 0] = av.x; sA[v][c4 + 1] = av.y;
            sA[v][c4 + 2] = av.z; sA[v][c4 + 3] = av.w;
        }
        {
            int c  = tid >> 4;
            int k4 = (tid & 15) * 4;
            float4 bv = *(const float4*)&Wx[(size_t)(kc + c) * K_SZ + col0 + k4];
            sB[c][k4 + 0] = bv.x; sB[c][k4 + 1] = bv.y;
            sB[c][k4 + 2] = bv.z; sB[c][k4 + 3] = bv.w;
        }
        __syncthreads();
        #pragma unroll
        for (int cc = 0; cc < 16; cc++) {
            float ar[4], br[4];
            #pragma unroll
            for (int u = 0; u < 4; u++) ar[u] = sA[ty * 4 + u][cc];
            #pragma unroll
            for (int w = 0; w < 4; w++) br[w] = sB[cc][tx * 4 + w];
            #pragma unroll
            for (int u = 0; u < 4; u++)
                #pragma unroll
                for (int w = 0; w < 4; w++)
                    acc[u][w] = fmaf(ar[u], br[w], acc[u][w]);
        }
        __syncthreads();
    }
    #pragma unroll
    for (int u = 0; u < 4; u++) {
        int r = row0 + ty * 4 + u;
        #pragma unroll
        for (int w = 0; w < 4; w++) {
            int c = col0 + tx * 4 + w;
            g_P[(size_t)r * K_SZ + c] = acc[u][w] + b[c];
        }
    }
}

// ---------------------------------------------------------------------------
// Kernel 3: persistent cluster recurrence.
//  - Wh in registers as packed f32x2 row-pairs; fma.rn.f32x2 mainloop.
//  - h SoA: h[buf][srcRank][rec][64]; warp seg consumes slice seg only.
//  - broadcast: reducers store register values DIRECTLY to all 8 CTAs via
//    st.shared::cluster.v2.f32; one release-arrive per warp per destination.
// ---------------------------------------------------------------------------
__device__ __forceinline__ int tpos(int s, int dir) {
    return dir ? ((s < T_STEPS - 1) ? (T_STEPS - 2 - s) : (T_STEPS - 1)) : s;
}

struct __align__(16) SmemRNN {
    float  h[2][CLUSTER_N][3][64];         // 12288 B  [buf][srcRank][rec][col]
    float4 part[2][8][64];                 // 16384 B
    float4 x4[2][64];                      //  2048 B
    unsigned long long bar[2][CLUSTER_N];  //   128 B
};

__global__ void __launch_bounds__(THREADS_RNN, 1) __cluster_dims__(CLUSTER_N, 1, 1)
rnn_kernel(const float* __restrict__ Wh,
           float* __restrict__ out,
           int writeHt) {
    __shared__ SmemRNN sm;
    cg::cluster_group cluster = cg::this_cluster();
    const int rank = (int)cluster.block_rank();
    const int cid  = blockIdx.x / CLUSTER_N;
    const int tid  = threadIdx.x;
    const int lane = tid & 31;
    const int w    = tid >> 5;          // warp id 0..7 == consumed srcRank
    const int jg   = rank * JPB;

    const int r0 = cid * 3, r1 = r0 + 1, r2 = r0 + 2;
    const int g0 = r0 >> 1, d0 = r0 & 1;
    const int g1 = r1 >> 1, d1 = r1 & 1;
    const int g2 = r2 >> 1, d2 = r2 & 1;

    const uint32_t bar_base = s2u(&sm.bar[0][0]);

    if (tid < 2 * CLUSTER_N) {
        MBARRIER_INIT(bar_base + tid * 8, CLUSTER_N);   // 8 arrivals per phase
    }

    // ---- weights into registers, packed as f32x2 row-pairs ----
    unsigned long long wa2[32], wb2[32];
    {
        const float* base = Wh + (size_t)(w * 64) * K_SZ + jg + lane;
        #pragma unroll
        for (int ii = 0; ii < 32; ii++) {
            float a_lo = base[(size_t)(2 * ii) * K_SZ];
            float a_hi = base[(size_t)(2 * ii + 1) * K_SZ];
            float b_lo = base[(size_t)(2 * ii) * K_SZ + 32];
            float b_hi = base[(size_t)(2 * ii + 1) * K_SZ + 32];
            wa2[ii] = packf2(a_lo, a_hi);
            wb2[ii] = packf2(b_lo, b_hi);
        }
    }
    // h0 = 0 (buffer 0)
    for (int i = tid; i < CLUSTER_N * 3 * 64; i += THREADS_RNN)
        (&sm.h[0][0][0][0])[i] = 0.f;
    // x prefetch for step 0
    if (tid < 64) {
        int jj = tid;
        sm.x4[0][jj] = make_float4(
            g_P[(size_t)g_idx[tpos(0, d0) * G_SZ + g0] * K_SZ + jg + jj],
            g_P[(size_t)g_idx[tpos(0, d1) * G_SZ + g1] * K_SZ + jg + jj],
            g_P[(size_t)g_idx[tpos(0, d2) * G_SZ + g2] * K_SZ + jg + jj],
            0.f);
    }
    __syncthreads();
    cluster.sync();   // barriers initialized cluster-wide

    // DSMEM addresses
    const uint32_t my_h = s2u(&sm.h[0][0][0][0]);
    uint32_t rem_h[CLUSTER_N];
    #pragma unroll
    for (int rk = 0; rk < CLUSTER_N; rk++)
        asm("mapa.shared::cluster.u32 %0, %1, %2;" : "=r"(rem_h[rk]) : "r"(my_h), "r"(rk));
    uint32_t arr_bar = 0;   // lane<8: base of destination-lane's bar array
    if (lane < CLUSTER_N)
        asm("mapa.shared::cluster.u32 %0, %1, %2;" : "=r"(arr_bar) : "r"(bar_base), "r"(lane));

    const uint32_t my_bar_w0 = bar_base + (0 * CLUSTER_N + w) * 8;
    const uint32_t my_bar_w1 = bar_base + (1 * CLUSTER_N + w) * 8;

    // reducer-lane geometry: lanes 0..11 -> (rec, colpair)
    const int rrec = lane >> 2;                 // 0..2
    const int rcol = w * 8 + (lane & 3) * 2;    // even column
    const int rg   = (rrec == 0) ? g0 : (rrec == 1) ? g1 : g2;
    const int rd   = (rrec == 0) ? d0 : (rrec == 1) ? d1 : d2;
    // prefetch-lane geometry: lanes 12..19 -> column jj
    const int pjj  = w * 8 + (lane - 12);

    int par0 = 0, par1 = 0;
    int p = 0;
    for (int s = 0; s < T_STEPS; s++) {
        // ---- wait only for this warp's slice ----
        if (s > 0) {
            if (p == 0) { MBARRIER_WAIT_PARITY_CL(my_bar_w0, par0); par0 ^= 1; }
            else        { MBARRIER_WAIT_PARITY_CL(my_bar_w1, par1); par1 ^= 1; }
        }

        // ---- phase 1: packed f32x2 FMAs over this warp's 64-row slice ----
        const float* hr = &sm.h[p][w][0][0];
        unsigned long long A0 = 0ull, A1 = 0ull, A2 = 0ull;
        unsigned long long C0 = 0ull, C1 = 0ull, C2 = 0ull;
        #pragma unroll
        for (int ii = 0; ii < 32; ii++) {
            unsigned long long h0 = *(const unsigned long long*)(hr + 0 * 64 + 2 * ii);
            unsigned long long h1 = *(const unsigned long long*)(hr + 1 * 64 + 2 * ii);
            unsigned long long h2 = *(const unsigned long long*)(hr + 2 * 64 + 2 * ii);
            ffma2(A0, h0, wa2[ii]);
            ffma2(A1, h1, wa2[ii]);
            ffma2(A2, h2, wa2[ii]);
            ffma2(C0, h0, wb2[ii]);
            ffma2(C1, h1, wb2[ii]);
            ffma2(C2, h2, wb2[ii]);
        }
        sm.part[p][w][lane]      = make_float4(sum2(A0), sum2(A1), sum2(A2), 0.f);
        sm.part[p][w][lane + 32] = make_float4(sum2(C0), sum2(C1), sum2(C2), 0.f);
        __syncthreads();

        const bool last = (s == T_STEPS - 1);
        const int np = 1 - p;
        if (lane < 12) {
            // ---- phase 2: per-warp reduce of 2 cols x 1 rec, tanh, bcast ----
            const float* pf = (const float*)&sm.part[p][0][0];
            float sa = 0.f, sb = 0.f;
            #pragma unroll
            for (int q = 0; q < 8; q++) {
                sa += pf[(q * 64 + rcol) * 4 + rrec];
                sb += pf[(q * 64 + rcol + 1) * 4 + rrec];
            }
            const float* xf = (const float*)&sm.x4[p][0];
            float va = tanhf(sa + xf[rcol * 4 + rrec]);
            float vb = tanhf(sb + xf[(rcol + 1) * 4 + rrec]);

            int tt = tpos(s, rd);
            *(float2*)&out[((size_t)tt * G_SZ + rg) * (2 * K_SZ) + rd * K_SZ + jg + rcol]
                = make_float2(va, vb);
            if (last && writeHt) {
                size_t hb0 = (size_t)T_STEPS * G_SZ * 2 * K_SZ;
                *(float2*)&out[hb0 + (size_t)rg * (2 * K_SZ) + rd * K_SZ + jg + rcol]
                    = make_float2(va, vb);
            }

            if (!last) {
                // direct DSMEM scatter: h[np][rank][rrec][rcol..rcol+1] at every rank
                uint32_t off = (uint32_t)(((np * CLUSTER_N + rank) * 3 + rrec) * 64 + rcol) * 4;
                #pragma unroll
                for (int rk = 0; rk < CLUSTER_N; rk++) {
                    asm volatile("st.shared::cluster.v2.f32 [%0], {%1, %2};"
                                 :: "r"(rem_h[rk] + off), "f"(va), "f"(vb) : "memory");
                }
            }
        } else if (lane >= 12 && lane < 20 && !last) {
            // ---- x prefetch for step s+1 ----
            int sn = s + 1;
            sm.x4[np][pjj] = make_float4(
                g_P[(size_t)g_idx[tpos(sn, d0) * G_SZ + g0] * K_SZ + jg + pjj],
                g_P[(size_t)g_idx[tpos(sn, d1) * G_SZ + g1] * K_SZ + jg + pjj],
                g_P[(size_t)g_idx[tpos(sn, d2) * G_SZ + g2] * K_SZ + jg + pjj],
                0.f);
        }
        __syncwarp();
        if (!last && lane < CLUSTER_N) {
            // one release-arrive per warp per destination CTA
            uint32_t rb = arr_bar + (uint32_t)((np * CLUSTER_N + rank) * 8);
            asm volatile("mbarrier.arrive.release.cluster.shared::cluster.b64 _, [%0];"
                         :: "r"(rb) : "memory");
        }
        p = np;
    }
}

// ---------------------------------------------------------------------------
extern "C" void kernel_launch(void* const* d_in, const int* in_sizes, int n_in,
                              void* d_out, int out_size) {
    const float* seq   = (const float*)d_in[0];  // (T, V)
    const int*   perms = (const int*)  d_in[1];  // (G, V)
    const float* We    = (const float*)d_in[2];  // (V, K)
    const float* Wx    = (const float*)d_in[3];  // (K, K)
    const float* Wh    = (const float*)d_in[4];  // (K, K)
    const float* b     = (const float*)d_in[5];  // (K,)
    float* out = (float*)d_out;
    (void)in_sizes; (void)n_in;

    long long need = (long long)T_STEPS * G_SZ * 2 * K_SZ + (long long)G_SZ * 2 * K_SZ;
    int writeHt = ((long long)out_size >= need) ? 1 : 0;

    token_kernel<<<T_STEPS, 256>>>(seq, perms);
    dim3 ggrid(K_SZ / 64, V_SZ / 64);
    gemm_P_kernel<<<ggrid, 256>>>(We, Wx, b);
    rnn_kernel<<<NBLOCKS, THREADS_RNN>>>(Wh, out, writeHt);
}

// round 5
// speedup vs baseline: 1.6596x; 1.6596x over previous
#include <cuda_runtime.h>
#include <cooperative_groups.h>
#include <cstdint>

namespace cg = cooperative_groups;

#define T_STEPS 2048
#define V_SZ    2048
#define G_SZ    24
#define K_SZ    512
#define CLUSTER_N 8
#define JPB     64              // columns of Wh per CTA
#define NCLUSTERS 16            // 16 clusters * 3 recurrences = 48
#define NBLOCKS (NCLUSTERS * CLUSTER_N)
#define THREADS_RNN 256
#define SLICE_BYTES (3 * 64 * 4)   // 768 B: one CTA's h contribution

// ---------------- mbarrier helpers ----------------
#define MBARRIER_INIT(addr, count) \
    asm volatile("mbarrier.init.shared.b64 [%0], %1;" :: "r"((uint32_t)(addr)), "r"((uint32_t)(count)) : "memory")

#define MBARRIER_EXPECT_TX(addr, bytes) \
    asm volatile("mbarrier.arrive.expect_tx.shared.b64 _, [%0], %1;" :: "r"((uint32_t)(addr)), "r"((uint32_t)(bytes)) : "memory")

#define MBARRIER_WAIT_PARITY(mbar_smem_addr, phase_parity) do { \
    uint32_t _mbar = (uint32_t)(mbar_smem_addr); \
    uint32_t _parity = (uint32_t)(phase_parity); \
    uint32_t _done; \
    asm volatile( \
        "{\n\t" \
        ".reg .pred p;\n\t" \
        "mbarrier.try_wait.parity.acquire.cta.shared::cta.b64 p, [%1], %2;\n\t" \
        "selp.b32 %0, 1, 0, p;\n\t" \
        "}" \
        : "=r"(_done) : "r"(_mbar), "r"(_parity) : "memory"); \
    if (!_done) { \
        asm volatile( \
            "{\n\t" \
            ".reg .pred P1;\n\t" \
            "WAIT_LOOP_%=:\n\t" \
            "mbarrier.try_wait.parity.acquire.cta.shared::cta.b64 P1, [%0], %1, 0x989680;\n\t" \
            "@P1 bra.uni WAIT_DONE_%=;\n\t" \
            "bra.uni WAIT_LOOP_%=;\n\t" \
            "WAIT_DONE_%=:\n\t" \
            "}" \
            :: "r"(_mbar), "r"(_parity) : "memory"); \
    } \
} while(0)

__device__ __forceinline__ uint32_t s2u(const void* p) {
    uint32_t a;
    asm("{ .reg .u64 t; cvta.to.shared.u64 t, %1; cvt.u32.u64 %0, t; }" : "=r"(a) : "l"(p));
    return a;
}

__device__ __forceinline__ void ffma2(unsigned long long& acc,
                                      unsigned long long h2,
                                      unsigned long long w2) {
    asm("fma.rn.f32x2 %0, %1, %2, %0;" : "+l"(acc) : "l"(h2), "l"(w2));
}

__device__ __forceinline__ unsigned long long packf2(float lo, float hi) {
    unsigned long long r;
    asm("mov.b64 %0, {%1, %2};" : "=l"(r) : "f"(lo), "f"(hi));
    return r;
}

__device__ __forceinline__ float sum2(unsigned long long acc) {
    float lo, hi;
    asm("mov.b64 {%0, %1}, %2;" : "=f"(lo), "=f"(hi) : "l"(acc));
    return lo + hi;
}

// Scratch (no cudaMalloc allowed)
__device__ float g_P[V_SZ * K_SZ];       // P = W_e @ Wx + b   (V, K)
__device__ int   g_idx[T_STEPS * G_SZ];  // idx[t,g] = perms[g, token_t]

// ---------------------------------------------------------------------------
// Kernel 1 (fused): token recovery + P = W_e @ Wx + b
// grid = (8, 32) = 256 blocks; block handles 8 token rows + one 64x64 P tile.
// ---------------------------------------------------------------------------
__global__ void __launch_bounds__(256)
prep_kernel(const float* __restrict__ seq,
            const int* __restrict__ perms,
            const float* __restrict__ We,
            const float* __restrict__ Wx,
            const float* __restrict__ b) {
    int tid = threadIdx.x;
    int wid = tid >> 5, lane = tid & 31;

    // ---- token part: warp wid scans one one-hot row ----
    {
        int bid = blockIdx.y * gridDim.x + blockIdx.x;   // 0..255
        int row = bid * 8 + wid;                          // 0..2047
        const float4* r4 = (const float4*)(seq + (size_t)row * V_SZ) + lane * 16;
        int found = -1;
        #pragma unroll
        for (int i = 0; i < 16; i++) {
            float4 v = r4[i];
            int base = lane * 64 + i * 4;
            if (v.x > 0.5f) found = base;
            if (v.y > 0.5f) found = base + 1;
            if (v.z > 0.5f) found = base + 2;
            if (v.w > 0.5f) found = base + 3;
        }
        int tok = __reduce_max_sync(0xffffffffu, found);
        if (lane < G_SZ)
            g_idx[row * G_SZ + lane] = perms[lane * V_SZ + tok];
    }

    // ---- GEMM part ----
    __shared__ float sA[64][17];
    __shared__ float sB[16][68];
    int tx = tid & 15, ty = tid >> 4;
    int row0 = blockIdx.y * 64;
    int col0 = blockIdx.x * 64;
    float acc[4][4] = {};

    for (int kc = 0; kc < K_SZ; kc += 16) {
        {
            int v  = tid >> 2;
            int c4 = (tid & 3) * 4;
            float4 av = *(const float4*)&We[(size_t)(row0 + v) * K_SZ + kc + c4];
            sA[v][c4 + 0] = av.x; sA[v][c4 + 1] = av.y;
            sA[v][c4 + 2] = av.z; sA[v][c4 + 3] = av.w;
        }
        {
            int c  = tid >> 4;
            int k4 = (tid & 15) * 4;
            float4 bv = *(const float4*)&Wx[(size_t)(kc + c) * K_SZ + col0 + k4];
            sB[c][k4 + 0] = bv.x; sB[c][k4 + 1] = bv.y;
            sB[c][k4 + 2] = bv.z; sB[c][k4 + 3] = bv.w;
        }
        __syncthreads();
        #pragma unroll
        for (int cc = 0; cc < 16; cc++) {
            float ar[4], br[4];
            #pragma unroll
            for (int u = 0; u < 4; u++) ar[u] = sA[ty * 4 + u][cc];
            #pragma unroll
            for (int w = 0; w < 4; w++) br[w] = sB[cc][tx * 4 + w];
            #pragma unroll
            for (int u = 0; u < 4; u++)
                #pragma unroll
                for (int w = 0; w < 4; w++)
                    acc[u][w] = fmaf(ar[u], br[w], acc[u][w]);
        }
        __syncthreads();
    }
    #pragma unroll
    for (int u = 0; u < 4; u++) {
        int r = row0 + ty * 4 + u;
        #pragma unroll
        for (int w = 0; w < 4; w++) {
            int c = col0 + tx * 4 + w;
            g_P[(size_t)r * K_SZ + c] = acc[u][w] + b[c];
        }
    }
}

// ---------------------------------------------------------------------------
// Kernel 2: persistent cluster recurrence (R3 transport + spread phase 2).
// ---------------------------------------------------------------------------
__device__ __forceinline__ int tpos(int s, int dir) {
    return dir ? ((s < T_STEPS - 1) ? (T_STEPS - 2 - s) : (T_STEPS - 1)) : s;
}

struct __align__(16) SmemRNN {
    float  h[2][CLUSTER_N][3][64];         // 12288 B  [buf][srcRank][rec][col]
    float4 part[2][8][64];                 // 16384 B
    float4 x4[2][64];                      //  2048 B
    float  stage[2][3][64];                //  1536 B
    unsigned long long bar[2][CLUSTER_N];  //   128 B
};

__global__ void __launch_bounds__(THREADS_RNN, 1) __cluster_dims__(CLUSTER_N, 1, 1)
rnn_kernel(const float* __restrict__ Wh,
           float* __restrict__ out,
           int writeHt) {
    __shared__ SmemRNN sm;
    cg::cluster_group cluster = cg::this_cluster();
    const int rank = (int)cluster.block_rank();
    const int cid  = blockIdx.x / CLUSTER_N;
    const int tid  = threadIdx.x;
    const int lane = tid & 31;
    const int w    = tid >> 5;          // warp id 0..7 == consumed srcRank
    const int jg   = rank * JPB;

    const int r0 = cid * 3;
    const int g0 = r0 >> 1,       d0 = r0 & 1;
    const int g1 = (r0 + 1) >> 1, d1 = (r0 + 1) & 1;
    const int g2 = (r0 + 2) >> 1, d2 = (r0 + 2) & 1;

    const uint32_t bar_base = s2u(&sm.bar[0][0]);

    if (tid < 2 * CLUSTER_N)
        MBARRIER_INIT(bar_base + tid * 8, 1);
    __syncthreads();
    // arm both buffers for this warp's slice (remote slices only)
    if (lane == 0 && w != rank) {
        MBARRIER_EXPECT_TX(bar_base + (0 * CLUSTER_N + w) * 8, SLICE_BYTES);
        MBARRIER_EXPECT_TX(bar_base + (1 * CLUSTER_N + w) * 8, SLICE_BYTES);
    }

    // ---- weights into registers, packed as f32x2 row-pairs ----
    unsigned long long wa2[32], wb2[32];
    {
        const float* base = Wh + (size_t)(w * 64) * K_SZ + jg + lane;
        #pragma unroll
        for (int ii = 0; ii < 32; ii++) {
            wa2[ii] = packf2(base[(size_t)(2 * ii) * K_SZ],
                             base[(size_t)(2 * ii + 1) * K_SZ]);
            wb2[ii] = packf2(base[(size_t)(2 * ii) * K_SZ + 32],
                             base[(size_t)(2 * ii + 1) * K_SZ + 32]);
        }
    }
    // h0 = 0 (buffer 0)
    for (int i = tid; i < CLUSTER_N * 3 * 64; i += THREADS_RNN)
        (&sm.h[0][0][0][0])[i] = 0.f;
    // x for step 0
    if (tid < 64) {
        int jj = tid;
        sm.x4[0][jj] = make_float4(
            g_P[(size_t)g_idx[tpos(0, d0) * G_SZ + g0] * K_SZ + jg + jj],
            g_P[(size_t)g_idx[tpos(0, d1) * G_SZ + g1] * K_SZ + jg + jj],
            g_P[(size_t)g_idx[tpos(0, d2) * G_SZ + g2] * K_SZ + jg + jj],
            0.f);
    }

    // prefetch-lane setup: lanes 24..31 own column pj; preload idx for s=1
    const bool plane = (lane >= 24);
    const int  pj    = w * 8 + (lane - 24);
    int tA = 0, tB = 0, tC = 0;
    if (plane) {
        tA = g_idx[tpos(1, d0) * G_SZ + g0];
        tB = g_idx[tpos(1, d1) * G_SZ + g1];
        tC = g_idx[tpos(1, d2) * G_SZ + g2];
    }
    __syncthreads();
    cluster.sync();   // barriers initialized & armed cluster-wide

    // issuer threads (tid 0..6): destination rank skipping self
    uint32_t rem_h_t = 0, rem_bar_t = 0;
    const uint32_t my_h     = s2u(&sm.h[0][0][0][0]);
    const uint32_t my_stage = s2u(&sm.stage[0][0][0]);
    if (tid < CLUSTER_N - 1) {
        int dst = tid + (tid >= rank ? 1 : 0);
        asm("mapa.shared::cluster.u32 %0, %1, %2;" : "=r"(rem_h_t)   : "r"(my_h),     "r"(dst));
        asm("mapa.shared::cluster.u32 %0, %1, %2;" : "=r"(rem_bar_t) : "r"(bar_base), "r"(dst));
    }
    const uint32_t my_bar_w0 = bar_base + (0 * CLUSTER_N + w) * 8;
    const uint32_t my_bar_w1 = bar_base + (1 * CLUSTER_N + w) * 8;

    // reducer-lane geometry: lanes 0..23 -> (rec, col)
    const int rrec = lane >> 3;              // 0..2 (lanes 0..23)
    const int rcol = w * 8 + (lane & 7);     // column within slice
    const int rr   = r0 + rrec;
    const int rg   = rr >> 1, rd = rr & 1;

    int par0 = 0, par1 = 0;
    int p = 0;
    for (int s = 0; s < T_STEPS; s++) {
        const bool last = (s == T_STEPS - 1);
        const int np = 1 - p;

        // ---- early x-gather issue for step s+1 (prefetch lanes) ----
        float vA = 0.f, vB = 0.f, vC = 0.f;
        if (plane && !last) {
            vA = g_P[(size_t)tA * K_SZ + jg + pj];
            vB = g_P[(size_t)tB * K_SZ + jg + pj];
            vC = g_P[(size_t)tC * K_SZ + jg + pj];
        }

        // ---- wait only for this warp's slice (remote only) ----
        if (s > 0 && w != rank) {
            if (p == 0) {
                MBARRIER_WAIT_PARITY(my_bar_w0, par0);
                if (lane == 0) MBARRIER_EXPECT_TX(my_bar_w0, SLICE_BYTES);
                par0 ^= 1;
            } else {
                MBARRIER_WAIT_PARITY(my_bar_w1, par1);
                if (lane == 0) MBARRIER_EXPECT_TX(my_bar_w1, SLICE_BYTES);
                par1 ^= 1;
            }
        }

        // ---- phase 1: f32x2 FMAs, h via broadcast LDS.128 ----
        const float* hr0 = &sm.h[p][w][0][0];
        const float* hr1 = &sm.h[p][w][1][0];
        const float* hr2 = &sm.h[p][w][2][0];
        unsigned long long A0 = 0ull, A1 = 0ull, A2 = 0ull;
        unsigned long long C0 = 0ull, C1 = 0ull, C2 = 0ull;
        #pragma unroll
        for (int ii = 0; ii < 16; ii++) {
            ulonglong2 H0 = *(const ulonglong2*)(hr0 + 4 * ii);
            ulonglong2 H1 = *(const ulonglong2*)(hr1 + 4 * ii);
            ulonglong2 H2 = *(const ulonglong2*)(hr2 + 4 * ii);
            ffma2(A0, H0.x, wa2[2 * ii]);     ffma2(A0, H0.y, wa2[2 * ii + 1]);
            ffma2(A1, H1.x, wa2[2 * ii]);     ffma2(A1, H1.y, wa2[2 * ii + 1]);
            ffma2(A2, H2.x, wa2[2 * ii]);     ffma2(A2, H2.y, wa2[2 * ii + 1]);
            ffma2(C0, H0.x, wb2[2 * ii]);     ffma2(C0, H0.y, wb2[2 * ii + 1]);
            ffma2(C1, H1.x, wb2[2 * ii]);     ffma2(C1, H1.y, wb2[2 * ii + 1]);
            ffma2(C2, H2.x, wb2[2 * ii]);     ffma2(C2, H2.y, wb2[2 * ii + 1]);
        }
        sm.part[p][w][lane]      = make_float4(sum2(A0), sum2(A1), sum2(A2), 0.f);
        sm.part[p][w][lane + 32] = make_float4(sum2(C0), sum2(C1), sum2(C2), 0.f);
        __syncthreads();

        // ---- phase 2 (spread over all warps) ----
        float va = 0.f;
        if (lane < 24) {
            const float* pf = (const float*)&sm.part[p][0][0];
            float sa = 0.f;
            #pragma unroll
            for (int q = 0; q < 8; q++)
                sa += pf[(q * 64 + rcol) * 4 + rrec];
            const float* xf = (const float*)&sm.x4[p][0];
            va = tanhf(sa + xf[rcol * 4 + rrec]);
            if (!last) {
                sm.stage[p][rrec][rcol] = va;
                sm.h[np][rank][rrec][rcol] = va;   // local slice shortcut
                asm volatile("fence.proxy.async.shared::cta;" ::: "memory");
            }
        } else if (plane && !last) {
            sm.x4[np][pj] = make_float4(vA, vB, vC, 0.f);
            // idx prefetch for step s+2
            int sf = (s + 2 < T_STEPS) ? s + 2 : T_STEPS - 1;
            tA = g_idx[tpos(sf, d0) * G_SZ + g0];
            tB = g_idx[tpos(sf, d1) * G_SZ + g1];
            tC = g_idx[tpos(sf, d2) * G_SZ + g2];
        }
        __syncthreads();

        // ---- issue 7 remote copies (768 B each) ----
        if (!last && tid < CLUSTER_N - 1) {
            uint32_t dst = rem_h_t + (uint32_t)((np * CLUSTER_N + rank) * SLICE_BYTES);
            uint32_t src = my_stage + (uint32_t)(p * SLICE_BYTES);
            uint32_t rb  = rem_bar_t + (uint32_t)((np * CLUSTER_N + rank) * 8);
            asm volatile(
                "cp.async.bulk.shared::cluster.shared::cta.mbarrier::complete_tx::bytes "
                "[%0], [%1], %2, [%3];"
                :: "r"(dst), "r"(src), "r"(SLICE_BYTES), "r"(rb) : "memory");
        }

        // ---- global stores (off the critical path) ----
        if (lane < 24) {
            int tt = tpos(s, rd);
            out[((size_t)tt * G_SZ + rg) * (2 * K_SZ) + rd * K_SZ + jg + rcol] = va;
            if (last && writeHt) {
                size_t hb0 = (size_t)T_STEPS * G_SZ * 2 * K_SZ;
                out[hb0 + (size_t)rg * (2 * K_SZ) + rd * K_SZ + jg + rcol] = va;
            }
        }
        p = np;
    }
}

// ---------------------------------------------------------------------------
extern "C" void kernel_launch(void* const* d_in, const int* in_sizes, int n_in,
                              void* d_out, int out_size) {
    const float* seq   = (const float*)d_in[0];  // (T, V)
    const int*   perms = (const int*)  d_in[1];  // (G, V)
    const float* We    = (const float*)d_in[2];  // (V, K)
    const float* Wx    = (const float*)d_in[3];  // (K, K)
    const float* Wh    = (const float*)d_in[4];  // (K, K)
    const float* b     = (const float*)d_in[5];  // (K,)
    float* out = (float*)d_out;
    (void)in_sizes; (void)n_in;

    long long need = (long long)T_STEPS * G_SZ * 2 * K_SZ + (long long)G_SZ * 2 * K_SZ;
    int writeHt = ((long long)out_size >= need) ? 1 : 0;

    dim3 ggrid(K_SZ / 64, V_SZ / 64);   // (8, 32) = 256 blocks = 2048 token rows
    prep_kernel<<<ggrid, 256>>>(seq, perms, We, Wx, b);
    rnn_kernel<<<NBLOCKS, THREADS_RNN>>>(Wh, out, writeHt);
}

// round 6
// speedup vs baseline: 2.2493x; 1.3553x over previous
#include <cuda_runtime.h>
#include <cooperative_groups.h>
#include <cstdint>

namespace cg = cooperative_groups;

#define T_STEPS 2048
#define V_SZ    2048
#define G_SZ    24
#define K_SZ    512
#define CLUSTER_N 8
#define JPB     64              // columns of Wh per CTA
#define NCLUSTERS 12            // 12 clusters * 2 groups * 2 recs = 48
#define NBLOCKS (NCLUSTERS * CLUSTER_N)
#define THREADS_RNN 256
#define RPG     2               // recurrences per group (fwd + bwd of one G-group)
#define SLICE_B (RPG * 64 * 4)  // 512 B: one CTA's h contribution per group

// ---------------- mbarrier helpers ----------------
#define MBARRIER_INIT(addr, count) \
    asm volatile("mbarrier.init.shared.b64 [%0], %1;" :: "r"((uint32_t)(addr)), "r"((uint32_t)(count)) : "memory")

#define MBARRIER_EXPECT_TX(addr, bytes) \
    asm volatile("mbarrier.arrive.expect_tx.shared.b64 _, [%0], %1;" :: "r"((uint32_t)(addr)), "r"((uint32_t)(bytes)) : "memory")

#define MBARRIER_WAIT_PARITY(mbar_smem_addr, phase_parity) do { \
    uint32_t _mbar = (uint32_t)(mbar_smem_addr); \
    uint32_t _parity = (uint32_t)(phase_parity); \
    uint32_t _done; \
    asm volatile( \
        "{\n\t" \
        ".reg .pred p;\n\t" \
        "mbarrier.try_wait.parity.acquire.cta.shared::cta.b64 p, [%1], %2;\n\t" \
        "selp.b32 %0, 1, 0, p;\n\t" \
        "}" \
        : "=r"(_done) : "r"(_mbar), "r"(_parity) : "memory"); \
    if (!_done) { \
        asm volatile( \
            "{\n\t" \
            ".reg .pred P1;\n\t" \
            "WAIT_LOOP_%=:\n\t" \
            "mbarrier.try_wait.parity.acquire.cta.shared::cta.b64 P1, [%0], %1, 0x989680;\n\t" \
            "@P1 bra.uni WAIT_DONE_%=;\n\t" \
            "bra.uni WAIT_LOOP_%=;\n\t" \
            "WAIT_DONE_%=:\n\t" \
            "}" \
            :: "r"(_mbar), "r"(_parity) : "memory"); \
    } \
} while(0)

__device__ __forceinline__ uint32_t s2u(const void* p) {
    uint32_t a;
    asm("{ .reg .u64 t; cvta.to.shared.u64 t, %1; cvt.u32.u64 %0, t; }" : "=r"(a) : "l"(p));
    return a;
}

__device__ __forceinline__ void ffma2(unsigned long long& acc,
                                      unsigned long long h2,
                                      unsigned long long w2) {
    asm("fma.rn.f32x2 %0, %1, %2, %0;" : "+l"(acc) : "l"(h2), "l"(w2));
}

__device__ __forceinline__ unsigned long long packf2(float lo, float hi) {
    unsigned long long r;
    asm("mov.b64 %0, {%1, %2};" : "=l"(r) : "f"(lo), "f"(hi));
    return r;
}

__device__ __forceinline__ float sum2(unsigned long long acc) {
    float lo, hi;
    asm("mov.b64 {%0, %1}, %2;" : "=f"(lo), "=f"(hi) : "l"(acc));
    return lo + hi;
}

// Scratch (no cudaMalloc allowed)
__device__ float g_P[V_SZ * K_SZ];       // P = W_e @ Wx + b   (V, K)
__device__ int   g_idx[T_STEPS * G_SZ];  // idx[t,g] = perms[g, token_t]

// ---------------------------------------------------------------------------
// Kernel 1 (fused): token recovery + P = W_e @ Wx + b
// ---------------------------------------------------------------------------
__global__ void __launch_bounds__(256)
prep_kernel(const float* __restrict__ seq,
            const int* __restrict__ perms,
            const float* __restrict__ We,
            const float* __restrict__ Wx,
            const float* __restrict__ b) {
    int tid = threadIdx.x;
    int wid = tid >> 5, lane = tid & 31;

    // ---- token part: warp wid scans one one-hot row ----
    {
        int bid = blockIdx.y * gridDim.x + blockIdx.x;   // 0..255
        int row = bid * 8 + wid;                          // 0..2047
        const float4* r4 = (const float4*)(seq + (size_t)row * V_SZ) + lane * 16;
        int found = -1;
        #pragma unroll
        for (int i = 0; i < 16; i++) {
            float4 v = r4[i];
            int base = lane * 64 + i * 4;
            if (v.x > 0.5f) found = base;
            if (v.y > 0.5f) found = base + 1;
            if (v.z > 0.5f) found = base + 2;
            if (v.w > 0.5f) found = base + 3;
        }
        int tok = __reduce_max_sync(0xffffffffu, found);
        if (lane < G_SZ)
            g_idx[row * G_SZ + lane] = perms[lane * V_SZ + tok];
    }

    // ---- GEMM part ----
    __shared__ float sA[64][17];
    __shared__ float sB[16][68];
    int tx = tid & 15, ty = tid >> 4;
    int row0 = blockIdx.y * 64;
    int col0 = blockIdx.x * 64;
    float acc[4][4] = {};

    for (int kc = 0; kc < K_SZ; kc += 16) {
        {
            int v  = tid >> 2;
            int c4 = (tid & 3) * 4;
            float4 av = *(const float4*)&We[(size_t)(row0 + v) * K_SZ + kc + c4];
            sA[v][c4 + 0] = av.x; sA[v][c4 + 1] = av.y;
            sA[v][c4 + 2] = av.z; sA[v][c4 + 3] = av.w;
        }
        {
            int c  = tid >> 4;
            int k4 = (tid & 15) * 4;
            float4 bv = *(const float4*)&Wx[(size_t)(kc + c) * K_SZ + col0 + k4];
            sB[c][k4 + 0] = bv.x; sB[c][k4 + 1] = bv.y;
            sB[c][k4 + 2] = bv.z; sB[c][k4 + 3] = bv.w;
        }
        __syncthreads();
        #pragma unroll
        for (int cc = 0; cc < 16; cc++) {
            float ar[4], br[4];
            #pragma unroll
            for (int u = 0; u < 4; u++) ar[u] = sA[ty * 4 + u][cc];
            #pragma unroll
            for (int w = 0; w < 4; w++) br[w] = sB[cc][tx * 4 + w];
            #pragma unroll
            for (int u = 0; u < 4; u++)
                #pragma unroll
                for (int w = 0; w < 4; w++)
                    acc[u][w] = fmaf(ar[u], br[w], acc[u][w]);
        }
        __syncthreads();
    }
    #pragma unroll
    for (int u = 0; u < 4; u++) {
        int r = row0 + ty * 4 + u;
        #pragma unroll
        for (int w = 0; w < 4; w++) {
            int c = col0 + tx * 4 + w;
            g_P[(size_t)r * K_SZ + c] = acc[u][w] + b[c];
        }
    }
}

// ---------------------------------------------------------------------------
// Kernel 2: persistent cluster recurrence, two-group ping-pong.
// Cluster handles G-groups (cid*2) and (cid*2+1), each with fwd+bwd recs.
// While group A's h-broadcast is in flight, group B computes (and vice versa).
// ---------------------------------------------------------------------------
__device__ __forceinline__ int tpos(int s, int dir) {
    return dir ? ((s < T_STEPS - 1) ? (T_STEPS - 2 - s) : (T_STEPS - 1)) : s;
}

struct __align__(16) SmemRNN {
    float  h[2][2][CLUSTER_N][RPG][64];        // 16384 B [grp][buf][src][rec][col]
    float2 part[8][64];                        //  4096 B (bracketed by syncs)
    float2 x2[2][2][64];                       //  2048 B [grp][buf][col]
    unsigned long long bar[2][2][CLUSTER_N];   //   256 B [grp][buf][src]
};

__global__ void __launch_bounds__(THREADS_RNN, 1) __cluster_dims__(CLUSTER_N, 1, 1)
rnn_kernel(const float* __restrict__ Wh,
           float* __restrict__ out,
           int writeHt) {
    __shared__ SmemRNN sm;
    cg::cluster_group cluster = cg::this_cluster();
    const int rank = (int)cluster.block_rank();
    const int cid  = blockIdx.x / CLUSTER_N;
    const int tid  = threadIdx.x;
    const int lane = tid & 31;
    const int w    = tid >> 5;          // warp id 0..7 == consumed srcRank
    const int jg   = rank * JPB;

    const uint32_t bar_base = s2u(&sm.bar[0][0][0]);
    if (tid < 2 * 2 * CLUSTER_N)
        MBARRIER_INIT(bar_base + tid * 8, 1);
    __syncthreads();
    // arm both buffers of both groups for this warp's slice (remote only)
    if (lane == 0 && w != rank) {
        #pragma unroll
        for (int gb = 0; gb < 4; gb++)
            MBARRIER_EXPECT_TX(bar_base + (uint32_t)((gb * CLUSTER_N + w) * 8), SLICE_B);
    }

    // ---- weights into registers, packed as f32x2 row-pairs (shared by groups)
    unsigned long long wa2[32], wb2[32];
    {
        const float* base = Wh + (size_t)(w * 64) * K_SZ + jg + lane;
        #pragma unroll
        for (int ii = 0; ii < 32; ii++) {
            wa2[ii] = packf2(base[(size_t)(2 * ii) * K_SZ],
                             base[(size_t)(2 * ii + 1) * K_SZ]);
            wb2[ii] = packf2(base[(size_t)(2 * ii) * K_SZ + 32],
                             base[(size_t)(2 * ii + 1) * K_SZ + 32]);
        }
    }
    // zero all h buffers
    for (int i = tid; i < 2 * 2 * CLUSTER_N * RPG * 64; i += THREADS_RNN)
        (&sm.h[0][0][0][0][0])[i] = 0.f;
    // x for step 0, both groups (fwd: t=0, bwd: t=T-2)
    if (tid < 64) {
        int c = tid;
        #pragma unroll
        for (int g = 0; g < 2; g++) {
            int gg = cid * 2 + g;
            sm.x2[g][0][c] = make_float2(
                g_P[(size_t)g_idx[0 * G_SZ + gg] * K_SZ + jg + c],
                g_P[(size_t)g_idx[(T_STEPS - 2) * G_SZ + gg] * K_SZ + jg + c]);
        }
    }
    // prefetch lanes: lanes 24..31 own column pj; preload idx for s=1
    const bool plane = (lane >= 24);
    const int  pj    = w * 8 + (lane - 24);
    int tF[2], tR[2];
    #pragma unroll
    for (int g = 0; g < 2; g++) {
        int gg = cid * 2 + g;
        tF[g] = g_idx[1 * G_SZ + gg];                 // tpos(1,0)=1
        tR[g] = g_idx[(T_STEPS - 3) * G_SZ + gg];     // tpos(1,1)=T-3
    }
    __syncthreads();
    cluster.sync();   // barriers initialized & armed cluster-wide

    // issuer threads (tid 0..6): destination rank skipping self
    uint32_t rem_h_t = 0, rem_bar_t = 0;
    const uint32_t my_h = s2u(&sm.h[0][0][0][0][0]);
    if (tid < CLUSTER_N - 1) {
        int dst = tid + (tid >= rank ? 1 : 0);
        asm("mapa.shared::cluster.u32 %0, %1, %2;" : "=r"(rem_h_t)   : "r"(my_h),     "r"(dst));
        asm("mapa.shared::cluster.u32 %0, %1, %2;" : "=r"(rem_bar_t) : "r"(bar_base), "r"(dst));
    }

    const size_t hb0 = (size_t)T_STEPS * G_SZ * 2 * K_SZ;
    int p = 0;
    for (int s = 0; s < T_STEPS; s++) {
        const bool last = (s == T_STEPS - 1);
        const int np = p ^ 1;
        // deterministic wait parity for buffer p at step s (s>=1)
        const int wpar = ((s >> 1) + 1 - (s & 1)) & 1;

        #pragma unroll
        for (int g = 0; g < 2; g++) {
            const int gg = cid * 2 + g;

            // ---- prefetch issue for step s+1 (prefetch lanes; latency-hidden)
            float vF = 0.f, vR = 0.f;
            if (plane && !last) {
                vF = g_P[(size_t)tF[g] * K_SZ + jg + pj];
                vR = g_P[(size_t)tR[g] * K_SZ + jg + pj];
            }

            // ---- wait only for this warp's slice (remote only) ----
            if (s > 0 && w != rank) {
                uint32_t wb = bar_base + (uint32_t)(((g * 2 + p) * CLUSTER_N + w) * 8);
                MBARRIER_WAIT_PARITY(wb, wpar);
                if (lane == 0) MBARRIER_EXPECT_TX(wb, SLICE_B);
            }

            // ---- phase 1: f32x2 FMAs, h via broadcast LDS.128 ----
            const float* hr0 = &sm.h[g][p][w][0][0];
            const float* hr1 = &sm.h[g][p][w][1][0];
            unsigned long long A0 = 0ull, A1 = 0ull, C0 = 0ull, C1 = 0ull;
            #pragma unroll
            for (int ii = 0; ii < 16; ii++) {
                ulonglong2 H0 = *(const ulonglong2*)(hr0 + 4 * ii);
                ulonglong2 H1 = *(const ulonglong2*)(hr1 + 4 * ii);
                ffma2(A0, H0.x, wa2[2 * ii]);  ffma2(A0, H0.y, wa2[2 * ii + 1]);
                ffma2(A1, H1.x, wa2[2 * ii]);  ffma2(A1, H1.y, wa2[2 * ii + 1]);
                ffma2(C0, H0.x, wb2[2 * ii]);  ffma2(C0, H0.y, wb2[2 * ii + 1]);
                ffma2(C1, H1.x, wb2[2 * ii]);  ffma2(C1, H1.y, wb2[2 * ii + 1]);
            }
            sm.part[w][lane]      = make_float2(sum2(A0), sum2(A1));
            sm.part[w][lane + 32] = make_float2(sum2(C0), sum2(C1));
            __syncthreads();

            // ---- phase 2: reduce, tanh, local h write (lanes 0..15) ----
            float va = 0.f;
            const int rrec = lane >> 3;              // 0=fwd, 1=bwd
            const int rcol = w * 8 + (lane & 7);
            if (lane < 16) {
                const float* pf = (const float*)&sm.part[0][0];
                float sa = 0.f;
                #pragma unroll
                for (int q = 0; q < 8; q++)
                    sa += pf[(q * 64 + rcol) * 2 + rrec];
                const float* xf = (const float*)&sm.x2[g][p][0];
                va = tanhf(sa + xf[rcol * 2 + rrec]);
                if (!last) {
                    sm.h[g][np][rank][rrec][rcol] = va;
                    asm volatile("fence.proxy.async.shared::cta;" ::: "memory");
                }
            }
            __syncthreads();

            // ---- issue 7 remote copies (512 B each) — not gated by stores below
            if (!last && tid < CLUSTER_N - 1) {
                uint32_t off = (uint32_t)(((g * 2 + np) * CLUSTER_N + rank) * SLICE_B);
                uint32_t rb  = rem_bar_t + (uint32_t)(((g * 2 + np) * CLUSTER_N + rank) * 8);
                asm volatile(
                    "cp.async.bulk.shared::cluster.shared::cta.mbarrier::complete_tx::bytes "
                    "[%0], [%1], %2, [%3];"
                    :: "r"(rem_h_t + off), "r"(my_h + off), "r"(SLICE_B), "r"(rb) : "memory");
            }

            // ---- tail: global out stores + x prefetch store (off critical path)
            if (lane < 16) {
                int tt = tpos(s, rrec);
                out[((size_t)tt * G_SZ + gg) * (2 * K_SZ) + rrec * K_SZ + jg + rcol] = va;
                if (last && writeHt)
                    out[hb0 + (size_t)gg * (2 * K_SZ) + rrec * K_SZ + jg + rcol] = va;
            } else if (plane && !last) {
                sm.x2[g][np][pj] = make_float2(vF, vR);
                int sf = (s + 2 < T_STEPS) ? s + 2 : T_STEPS - 1;
                tF[g] = g_idx[tpos(sf, 0) * G_SZ + gg];
                tR[g] = g_idx[tpos(sf, 1) * G_SZ + gg];
            }
        }
        p = np;
    }
}

// ---------------------------------------------------------------------------
extern "C" void kernel_launch(void* const* d_in, const int* in_sizes, int n_in,
                              void* d_out, int out_size) {
    const float* seq   = (const float*)d_in[0];  // (T, V)
    const int*   perms = (const int*)  d_in[1];  // (G, V)
    const float* We    = (const float*)d_in[2];  // (V, K)
    const float* Wx    = (const float*)d_in[3];  // (K, K)
    const float* Wh    = (const float*)d_in[4];  // (K, K)
    const float* b     = (const float*)d_in[5];  // (K,)
    float* out = (float*)d_out;
    (void)in_sizes; (void)n_in;

    long long need = (long long)T_STEPS * G_SZ * 2 * K_SZ + (long long)G_SZ * 2 * K_SZ;
    int writeHt = ((long long)out_size >= need) ? 1 : 0;

    dim3 ggrid(K_SZ / 64, V_SZ / 64);   // (8, 32) = 256 blocks
    prep_kernel<<<ggrid, 256>>>(seq, perms, We, Wx, b);
    rnn_kernel<<<NBLOCKS, THREADS_RNN>>>(Wh, out, writeHt);
}